// round 16
// baseline (speedup 1.0000x reference)
#include <cuda_runtime.h>

#define NV 2000
#define EV 64
#define NB 148            // persistent blocks: 4 col-quarters x 37 row-ranges
#define NTHR 512
#define NROWBLK 143
#define RPB 14
#define QCOLS 500
#define NRR 37
#define ZCAP 32
#define ZLCAP 256
#define NBAR 5

// ---------------- device scratch ----------------
__device__ float g_mu[2][NV * EV];           // written only when zeros exist
__device__ float g_csp[4][NB][EV];           // per-block column-sum partials
__device__ float g_cs_part[NRR][2048];       // colsum partials (one writer per cell)
__device__ float g_abs_part[64][NRR][2048];  // abs-sum partials
__device__ int   g_zc[NB];
__device__ int2  g_zpos[NB][ZCAP];
__device__ unsigned g_flags[NB];
__device__ unsigned g_bar_gen;

__device__ __forceinline__ void record_zero(int a, int b) {
    int p = atomicAdd(&g_zc[blockIdx.x], 1);
    if (p < ZCAP) {
        g_zpos[blockIdx.x][p].x = a;
        g_zpos[blockIdx.x][p].y = b;
    }
}

// ---------------- flag-array grid barrier (monotonic targets) ----------------
__device__ __forceinline__ void gbar(unsigned target, int blk, int tid) {
    __syncthreads();
    if (tid == 0) {
        __threadfence();
        *(volatile unsigned*)&g_flags[blk] = target;
    }
    if (blk == 0) {
        if (tid < NB)
            while ((int)(*(volatile unsigned*)&g_flags[tid] - target) < 0) { }
        __syncthreads();
        if (tid == 0) {
            __threadfence();
            *(volatile unsigned*)&g_bar_gen = target;
            __threadfence();
        }
    } else if (tid == 0) {
        while ((int)(*(volatile unsigned*)&g_bar_gen - target) < 0) { }
        __threadfence();
    }
    __syncthreads();
}

// pure register streaming down one column: NK knees (+ colsum/zero-detect)
template<int NK, bool CS>
__device__ __forceinline__ void stream_col(const float* __restrict__ W,
                                           int a0, int a1, int cg,
                                           const float* th, float* acc,
                                           float& acs) {
    const float* p = W + (long long)a0 * NV + cg;
    #pragma unroll 4
    for (int a = a0; a < a1; a++) {
        float w = __ldg(p);
        p += NV;
        if (CS) {
            acs += w;
            if (w <= 0.f) record_zero(a, cg);
        }
        #pragma unroll
        for (int i = 0; i < NK; i++)
            acc[i] += fabsf(w - th[i]);
    }
}

// ---------------- the one kernel ----------------
__global__ void __launch_bounds__(NTHR, 1) fused_kernel(
    const float* __restrict__ xv,  const float* __restrict__ W,
    const float* __restrict__ t1w, const float* __restrict__ t1b,
    const float* __restrict__ t2w, const float* __restrict__ t2b,
    const float* __restrict__ t3w, const float* __restrict__ t3b,
    const float* __restrict__ t4w, const float* __restrict__ t4b,
    const float* __restrict__ t5w, const float* __restrict__ t5b,
    const float* __restrict__ t6w, const float* __restrict__ t6b,
    const float* __restrict__ t7w, const float* __restrict__ t7b,
    float* __restrict__ out)
{
    __shared__ __align__(16) char smem_raw[29696];
    int tid = threadIdx.x;
    int blk = blockIdx.x;
    int e = tid & 63;
    int grp = tid >> 6;          // 0..7
    int j0 = blk * RPB;

    // shared map
    float* zone = (float*)smem_raw;                      // 16 KB weights
    float (*sx)[EV] = (float(*)[EV])(smem_raw + 16384);  // A only (3584)
    float* sr   = (float*)(smem_raw + 19968);            // B2 r; reused as smu
    float (*smu)[EV] = (float(*)[EV])(smem_raw + 19968);
    float* ssc  = (float*)(smem_raw + 23552);
    float* ssv  = (float*)(smem_raw + 23808);
    float (*sscp)[EV] = (float(*)[EV])(smem_raw + 24064); // 2048
    float* sca  = (float*)(smem_raw + 26112);
    float* scb  = (float*)(smem_raw + 26368);
    float* scc  = (float*)(smem_raw + 26624);
    int*   skx  = (int*)  (smem_raw + 26880);
    float* sth  = (float*)(smem_raw + 27136);
    unsigned* smk = (unsigned*)(smem_raw + 27392);       // masks + K
    int2*  s_zl = (int2*)(smem_raw + 27424);             // 2048
    unsigned* s_base = (unsigned*)(smem_raw + 29472);
    int*   s_nz  = (int*)(smem_raw + 29480);
    float (*swsum)[2] = (float(*)[2])(smem_raw + 26112); // D reuse
    float* sgg  = (float*)(smem_raw + 26368);            // D reuse

    float breg0 = 0.f, breg1 = 0.f;

    // ===================== Phase A (no global sync needed after) ==========
    {
        if (tid == 0) {
            s_base[0] = *(volatile unsigned*)&g_flags[blk];
            g_zc[blk] = 0;
            s_nz[0] = 0;
        }
        // classification step 1
        if (tid < 64) {
            float w4v = t4w[tid], b4v = t4b[tid];
            float ca = 0.f, cb = 0.f, cc = 0.f, th = 0.f;
            int interior = 0;
            if (w4v == 0.f) {
                cb = (float)NV * fmaxf(b4v, 0.f);
            } else {
                th = -b4v / w4v;
                if (th > 0.f && th < 1.f) {
                    interior = 1;
                    ca = 0.5f * w4v;
                    cb = 0.5f * (float)NV * b4v;
                    cc = 0.5f * fabsf(w4v);
                } else {
                    bool act = (w4v > 0.f) ? (th <= 0.f) : (th >= 1.f);
                    ca = act ? w4v : 0.f;
                    cb = act ? (float)NV * b4v : 0.f;
                }
            }
            unsigned m = __ballot_sync(0xffffffffu, interior);
            if ((tid & 31) == 0) smk[tid >> 5] = m;
            sca[tid] = ca; scb[tid] = cb; scc[tid] = cc;
            sth[tid] = 0.5f;
            skx[tid] = -1;
            ssv[tid] = th;               // temp
            ((int*)ssc)[tid] = interior; // temp
        }
        __syncthreads();
        // classification step 2: slot assignment
        if (tid < 64) {
            unsigned m0 = smk[0], m1 = smk[1];
            int lane = tid & 31;
            int interior = ((int*)ssc)[tid];
            unsigned m = (tid < 32) ? m0 : m1;
            int slot = __popc(m & ((1u << lane) - 1u)) + ((tid >= 32) ? __popc(m0) : 0);
            if (interior) {
                skx[tid] = slot;
                sth[slot] = ssv[tid];
            }
            if (tid == 0) smk[2] = __popc(m0) + __popc(m1);   // K
        }

        // base matmul (rows j0..j0+13)
        float* s1w = zone;
        if (blk < NROWBLK) {
            for (int i = tid; i < EV * EV; i += NTHR) s1w[i] = t1w[i];
            for (int i = tid; i < RPB * EV; i += NTHR) {
                int jj = i >> 6, k = i & 63;
                int j = j0 + jj;
                sx[jj][k] = (j < NV) ? xv[j * EV + k] : 0.f;
            }
            __syncthreads();
            #pragma unroll
            for (int p = 0; p < 2; p++) {
                int jj = grp + p * 8;
                int j = j0 + jj;
                if (jj < RPB && j < NV) {
                    float acc = t1b[e] + t3b[e];
                    #pragma unroll
                    for (int k = 0; k < EV; k++)
                        acc = fmaf(sx[jj][k], s1w[k * EV + e], acc);
                    if (p == 0) breg0 = acc; else breg1 = acc;
                }
            }
        } else {
            __syncthreads();
        }
    }
    unsigned base = s_base[0];

    // ===================== Phase B: stream W -> private partials ==========
    {
        int q  = blk / NRR;
        int rr = blk % NRR;
        int c0 = q * QCOLS;
        int a0 = rr * NV / NRR;
        int a1 = (rr + 1) * NV / NRR;
        int K = (int)smk[2];

        int cg = c0 + tid;
        bool colok = (tid < QCOLS);

        int kb = 0;
        do {
            int nk = K - kb; if (nk > 24) nk = 24; if (nk < 0) nk = 0;
            int nk8 = (nk + 7) & ~7;
            float th[24], acc[24], acs = 0.f;
            #pragma unroll
            for (int i = 0; i < 24; i++) {
                th[i] = (kb + i < K) ? sth[kb + i] : 0.5f;
                acc[i] = 0.f;
            }
            bool first = (kb == 0);

            if (colok) {
                if (first) {
                    switch (nk8) {
                        case 0:  stream_col<0,  true>(W, a0, a1, cg, th, acc, acs); break;
                        case 8:  stream_col<8,  true>(W, a0, a1, cg, th, acc, acs); break;
                        case 16: stream_col<16, true>(W, a0, a1, cg, th, acc, acs); break;
                        default: stream_col<24, true>(W, a0, a1, cg, th, acc, acs); break;
                    }
                } else {
                    switch (nk8) {
                        case 8:  stream_col<8,  false>(W, a0, a1, cg, th, acc, acs); break;
                        case 16: stream_col<16, false>(W, a0, a1, cg, th, acc, acs); break;
                        default: stream_col<24, false>(W, a0, a1, cg, th, acc, acs); break;
                    }
                }
                if (first) g_cs_part[rr][cg] = acs;
                for (int i = 0; i < nk; i++)
                    g_abs_part[kb + i][rr][cg] = acc[i];
            }
            kb += 24;
        } while (kb < K);
    }
    gbar(base + 1, blk, tid);   // barrier 1

    // merged zero list -> shared
    if (tid < NB) {
        int c = g_zc[tid]; if (c > ZCAP) c = ZCAP;
        if (c > 0) {
            int p = atomicAdd(s_nz, c);
            for (int z = 0; z < c; z++)
                if (p + z < ZLCAP) s_zl[p + z] = g_zpos[tid][z];
        }
    }
    __syncthreads();
    int nz0 = s_nz[0]; if (nz0 > ZLCAP) nz0 = ZLCAP;

    // ===================== Phase B2 + mu0 =====================
    {
        float csum = 0.f;
        if (blk < NROWBLK) {
            float* s3w = zone;
            for (int i = tid; i < EV * EV; i += NTHR) s3w[i] = t3w[i];
            __syncthreads();
            for (int i = tid; i < RPB * EV; i += NTHR) {
                int jj = i >> 6, ee = i & 63;
                int j = j0 + jj;
                float v = 0.f;
                if (j < NV) {
                    int kx = skx[ee];
                    const float* csp = &g_cs_part[0][j];
                    const float* abp = (kx >= 0) ? &g_abs_part[kx][0][j] : csp;
                    float S = 0.f, AB = 0.f;
                    #pragma unroll 4
                    for (int r2 = 0; r2 < NRR; r2++) {
                        S  += csp[r2 * 2048];
                        AB += abp[r2 * 2048];
                    }
                    v = sca[ee] * S + scb[ee];
                    if (kx >= 0) v += scc[ee] * AB;
                }
                sr[jj * 64 + ee] = v;
            }
            __syncthreads();

            float v0 = t2b[e];
            #pragma unroll
            for (int p = 0; p < 2; p++) {
                int jj = grp + p * 8;
                int j = j0 + jj;
                if (jj < RPB && j < NV) {
                    float acc = (p == 0) ? breg0 : breg1;
                    #pragma unroll
                    for (int k = 0; k < EV; k++)
                        acc = fmaf(sr[jj * 64 + k], zone[k * EV + e], acc);
                    if (p == 0) breg0 = acc; else breg1 = acc;
                    float m = fmaxf(acc + v0, 0.f);
                    if (nz0 > 0) g_mu[0][j * EV + e] = m;
                    csum += m;
                }
            }
        }
        sscp[grp][e] = csum;
        __syncthreads();
        if (tid < EV) {
            float s = 0.f;
            #pragma unroll
            for (int s8 = 0; s8 < 8; s8++) s += sscp[s8][tid];
            g_csp[0][blk][tid] = s;
        }
    }
    gbar(base + 2, blk, tid);   // barrier 2

    // ===================== Phase C: t = 1..3 =====================
    {
        float* st2w = zone;
        for (int i = tid; i < EV * EV; i += NTHR) st2w[i] = t2w[i];

        for (int t = 1; t < 4; t++) {
            // v = csum_{t-1} @ t2w + t2b (partials reduced in parallel)
            {
                float s = 0.f;
                for (int b = grp; b < NB; b += 8) s += g_csp[t - 1][b][e];
                sscp[grp][e] = s;
            }
            __syncthreads();
            if (tid < EV) {
                float s = 0.f;
                #pragma unroll
                for (int s8 = 0; s8 < 8; s8++) s += sscp[s8][tid];
                ssc[tid] = s;
            }
            __syncthreads();
            {
                float a = 0.f;
                #pragma unroll
                for (int k = 0; k < 8; k++) {
                    int kk = grp * 8 + k;
                    a = fmaf(ssc[kk], st2w[kk * EV + e], a);
                }
                sscp[grp][e] = a;
            }
            __syncthreads();
            if (tid < EV) {
                float s = t2b[tid];
                #pragma unroll
                for (int s8 = 0; s8 < 8; s8++) s += sscp[s8][tid];
                ssv[tid] = s;
            }
            __syncthreads();

            float csum = 0.f;
            if (blk < NROWBLK) {
                int prev = (t - 1) & 1;
                float v = ssv[e];
                #pragma unroll
                for (int p = 0; p < 2; p++) {
                    int jj = grp + p * 8;
                    int j = j0 + jj;
                    if (jj < RPB && j < NV) {
                        float corr = 0.f;
                        if (nz0 > 0) {
                            for (int z = 0; z < nz0; z++) {
                                int2 zp = s_zl[z];
                                if (zp.x == j) {
                                    float a2 = 0.f;
                                    for (int k = 0; k < EV; k++)
                                        a2 = fmaf(g_mu[prev][zp.y * EV + k],
                                                  st2w[k * EV + e], a2);
                                    corr += a2;
                                }
                            }
                        }
                        float bs = (p == 0) ? breg0 : breg1;
                        float m = fmaxf(bs + v - corr, 0.f);
                        if (nz0 > 0) g_mu[t & 1][j * EV + e] = m;
                        if (t == 3) smu[jj][e] = m;
                        csum += m;
                    }
                }
            }
            sscp[grp][e] = csum;
            __syncthreads();
            if (tid < EV) {
                float s = 0.f;
                #pragma unroll
                for (int s8 = 0; s8 < 8; s8++) s += sscp[s8][tid];
                g_csp[t][blk][tid] = s;
            }
            gbar(base + 2 + t, blk, tid);   // barriers 3..5
        }
    }

    // ===================== Phase D: final head =====================
    if (blk < NROWBLK) {
        float* s7w = zone;
        for (int i = tid; i < EV * EV; i += NTHR) s7w[i] = t7w[i];
        {
            float s = 0.f;
            for (int b = grp; b < NB; b += 8) s += g_csp[3][b][e];
            sscp[grp][e] = s;
        }
        __syncthreads();
        if (tid < EV) {
            float s = 0.f;
            #pragma unroll
            for (int s8 = 0; s8 < 8; s8++) s += sscp[s8][tid];
            ssc[tid] = s;
        }
        __syncthreads();
        if (tid < EV) {
            float a = t6b[tid];
            #pragma unroll
            for (int k = 0; k < EV; k++)
                a = fmaf(ssc[k], t6w[k * EV + tid], a);
            ssv[tid] = fmaxf(a, 0.f) * t5w[tid];
        }
        __syncthreads();
        if (tid == 0) {
            float gg = 0.f;
            #pragma unroll
            for (int k = 0; k < EV; k++) gg += ssv[k];
            sgg[0] = gg;
        }
        __syncthreads();

        float red[2];
        #pragma unroll
        for (int p = 0; p < 2; p++) {
            int jj = grp + p * 8;
            int j = j0 + jj;
            float val = 0.f;
            if (jj < RPB && j < NV) {
                float acc = t7b[e];
                #pragma unroll
                for (int k = 0; k < EV; k++)
                    acc = fmaf(smu[jj][k], s7w[k * EV + e], acc);
                val = fmaxf(acc, 0.f) * t5w[EV + e];
            }
            #pragma unroll
            for (int off = 16; off; off >>= 1)
                val += __shfl_xor_sync(0xffffffffu, val, off);
            red[p] = val;
        }
        int warp = tid >> 5, lane = tid & 31;
        if (lane == 0) {
            swsum[warp][0] = red[0];
            swsum[warp][1] = red[1];
        }
        __syncthreads();
        if (tid < 16) {
            int g8 = tid & 7, p = tid >> 3;
            int jj = g8 + p * 8;
            int j = j0 + jj;
            if (jj < RPB && j < NV)
                out[j] = sgg[0] + t5b[0]
                       + swsum[2 * g8][p] + swsum[2 * g8 + 1][p];
        }
    }
}

// ---------------- host launch ----------------
extern "C" void kernel_launch(void* const* d_in, const int* in_sizes, int n_in,
                              void* d_out, int out_size) {
    const float* xv  = (const float*)d_in[0];
    const float* W   = (const float*)d_in[1];
    const float* t1w = (const float*)d_in[2];
    const float* t1b = (const float*)d_in[3];
    const float* t2w = (const float*)d_in[4];
    const float* t2b = (const float*)d_in[5];
    const float* t3w = (const float*)d_in[6];
    const float* t3b = (const float*)d_in[7];
    const float* t4w = (const float*)d_in[8];
    const float* t4b = (const float*)d_in[9];
    const float* t5w = (const float*)d_in[10];
    const float* t5b = (const float*)d_in[11];
    const float* t6w = (const float*)d_in[12];
    const float* t6b = (const float*)d_in[13];
    const float* t7w = (const float*)d_in[14];
    const float* t7b = (const float*)d_in[15];
    float* out = (float*)d_out;

    fused_kernel<<<NB, NTHR>>>(xv, W, t1w, t1b, t2w, t2b, t3w, t3b,
                               t4w, t4b, t5w, t5b, t6w, t6b, t7w, t7b, out);
}